// round 13
// baseline (speedup 1.0000x reference)
#include <cuda_runtime.h>
#include <cuda_bf16.h>
#include <cstdint>

#define NBATCH 131072
#define NH   100
#define SP   120           // W2 tile pitch (bf16) = 240B, ldmatrix conflict-free
#define SPB  (SP * 2)
#define TPB  128
#define TILEB 64
#define NPASS 6
#define KT   7             // k16 tiles
#define NT   13            // n8 tiles (104 >= 100)
#define NTP  7

// ---- SMEM layout ----
#define SM_SCR   0                      // 4 warps x 26 slots x 32 lanes x 8B = 26624
#define SM_W2    26624                  // 112 x SP bf16 = 26880 (b2 folded in col 104)
#define SM_W1H   53504                  // 128 rows x 16B = 2048
#define SM_W3    55552                  // packed bf16x2 w3: 256
#define SM_W1G0  55808                  // 16 rows x 240B = 3840 (double buffered)
#define SM_W1G1  59648                  // 3840
#define SM_TOTAL 63488                  // 2 CTAs/SM (register-limited)

// ---- weight blob: [ W2 | W1H | W3pk ] (region A) + [ W1G ] (region B) ----
#define OB_W1H 26880
#define OB_W3  28928
#define REGA_BYTES 29184
#define OB_W1G 29184
#define BLOB_BYTES 33024

__device__ __align__(16) unsigned char g_blob[NPASS][BLOB_BYTES];

__device__ __forceinline__ uint32_t smem_u32(const void* p) {
    uint32_t a;
    asm("{ .reg .u64 t; cvta.to.shared.u64 t, %1; cvt.u32.u64 %0, t; }" : "=r"(a) : "l"(p));
    return a;
}
__device__ __forceinline__ void ldsm4(uint32_t* r, uint32_t addr) {
    asm volatile("ldmatrix.sync.aligned.m8n8.x4.shared.b16 {%0,%1,%2,%3}, [%4];"
                 : "=r"(r[0]), "=r"(r[1]), "=r"(r[2]), "=r"(r[3]) : "r"(addr));
}
__device__ __forceinline__ void ldsm4t(uint32_t* r, uint32_t addr) {
    asm volatile("ldmatrix.sync.aligned.m8n8.x4.trans.shared.b16 {%0,%1,%2,%3}, [%4];"
                 : "=r"(r[0]), "=r"(r[1]), "=r"(r[2]), "=r"(r[3]) : "r"(addr));
}
__device__ __forceinline__ void mma16816(float* d, const uint32_t* a, uint32_t b0, uint32_t b1) {
    asm volatile("mma.sync.aligned.m16n8k16.row.col.f32.bf16.bf16.f32 "
                 "{%0,%1,%2,%3}, {%4,%5,%6,%7}, {%8,%9}, {%0,%1,%2,%3};"
                 : "+f"(d[0]), "+f"(d[1]), "+f"(d[2]), "+f"(d[3])
                 : "r"(a[0]), "r"(a[1]), "r"(a[2]), "r"(a[3]), "r"(b0), "r"(b1));
}
__device__ __forceinline__ void mma16816i(float* d, const uint32_t* a, uint32_t b0, uint32_t b1,
                                          const float* c) {
    asm volatile("mma.sync.aligned.m16n8k16.row.col.f32.bf16.bf16.f32 "
                 "{%0,%1,%2,%3}, {%4,%5,%6,%7}, {%8,%9}, {%10,%11,%12,%13};"
                 : "=f"(d[0]), "=f"(d[1]), "=f"(d[2]), "=f"(d[3])
                 : "r"(a[0]), "r"(a[1]), "r"(a[2]), "r"(a[3]), "r"(b0), "r"(b1),
                   "f"(c[0]), "f"(c[1]), "f"(c[2]), "f"(c[3]));
}
__device__ __forceinline__ void mma16808i(float* d, uint32_t a0, uint32_t a1, uint32_t b0,
                                          const float* c) {
    asm volatile("mma.sync.aligned.m16n8k8.row.col.f32.bf16.bf16.f32 "
                 "{%0,%1,%2,%3}, {%4,%5}, {%6}, {%7,%8,%9,%10};"
                 : "=f"(d[0]), "=f"(d[1]), "=f"(d[2]), "=f"(d[3])
                 : "r"(a0), "r"(a1), "r"(b0),
                   "f"(c[0]), "f"(c[1]), "f"(c[2]), "f"(c[3]));
}
__device__ __forceinline__ void cp16(uint32_t smem_dst, const void* gsrc) {
    asm volatile("cp.async.cg.shared.global [%0], [%1], 16;"
                 :: "r"(smem_dst), "l"(gsrc));
}
__device__ __forceinline__ uint32_t pack_bf2(float a, float b) {
    __nv_bfloat162 t = __floats2bfloat162_rn(a, b);
    return *reinterpret_cast<uint32_t*>(&t);
}
__device__ __forceinline__ uint32_t hmul2u(uint32_t a, uint32_t b) {
    __nv_bfloat162 r = __hmul2(*reinterpret_cast<__nv_bfloat162*>(&a),
                               *reinterpret_cast<__nv_bfloat162*>(&b));
    return *reinterpret_cast<uint32_t*>(&r);
}
__device__ __forceinline__ uint32_t hfma2u(uint32_t a, uint32_t b, uint32_t c) {
    __nv_bfloat162 r = __hfma2(*reinterpret_cast<__nv_bfloat162*>(&a),
                               *reinterpret_cast<__nv_bfloat162*>(&b),
                               *reinterpret_cast<__nv_bfloat162*>(&c));
    return *reinterpret_cast<uint32_t*>(&r);
}
#define NEGH2 0xBF00BF00u   // bf16x2 {-0.5,-0.5}
#define ONE2  0x3F803F80u   // bf16x2 {1,1}
#define M6TH  0xBE2BBE2Bu   // bf16x2 {-1/6,-1/6}

// s = h(1 - h^2/6) in packed bf16x2; store to warp-private scratch
__device__ __forceinline__ void sin_tile(const float* a4, uint32_t* s2, uint32_t scr) {
    uint32_t h01 = pack_bf2(a4[0], a4[1]);
    uint32_t h23 = pack_bf2(a4[2], a4[3]);
    s2[0] = hmul2u(h01, hfma2u(hmul2u(h01, h01), M6TH, ONE2));
    s2[1] = hmul2u(h23, hfma2u(hmul2u(h23, h23), M6TH, ONE2));
    asm volatile("st.shared.v2.u32 [%0], {%1,%2};" :: "r"(scr), "r"(s2[0]), "r"(s2[1]));
}
// g2 = (1 - h^2/2) * w3
__device__ __forceinline__ void g2_tile(const float* a4, uint32_t wpk, uint32_t* o2) {
    uint32_t h01 = pack_bf2(a4[0], a4[1]);
    uint32_t h23 = pack_bf2(a4[2], a4[3]);
    o2[0] = hmul2u(hfma2u(hmul2u(h01, h01), NEGH2, ONE2), wpk);
    o2[1] = hmul2u(hfma2u(hmul2u(h23, h23), NEGH2, ONE2), wpk);
}
// g1 = gc * (1 - s^2/2), s from scratch
__device__ __forceinline__ void g1_tile(const float* a4, uint32_t scr, uint32_t* o2) {
    uint32_t u01, u23;
    asm("ld.shared.v2.u32 {%0,%1}, [%2];" : "=r"(u01), "=r"(u23) : "r"(scr));
    uint32_t c01 = hfma2u(hmul2u(u01, u01), NEGH2, ONE2);
    uint32_t c23 = hfma2u(hmul2u(u23, u23), NEGH2, ONE2);
    o2[0] = hmul2u(pack_bf2(a4[0], a4[1]), c01);
    o2[1] = hmul2u(pack_bf2(a4[2], a4[3]), c23);
}

// ------------------------------------------------------------------
__global__ void prep_kernel(
    const float* __restrict__ Wq1, const float* __restrict__ bq1,
    const float* __restrict__ Wq2, const float* __restrict__ bq2,
    const float* __restrict__ wq3,
    const float* __restrict__ Wp1, const float* __restrict__ bp1,
    const float* __restrict__ Wp2, const float* __restrict__ bp2,
    const float* __restrict__ wp3)
{
    const int net = blockIdx.x, layer = net >> 1, ph = net & 1;
    const float* W1 = (ph ? Wp1 : Wq1) + layer * NH * 3;
    const float* b1 = (ph ? bp1 : bq1) + layer * NH;
    const float* W2 = (ph ? Wp2 : Wq2) + layer * NH * NH;
    const float* b2 = (ph ? bp2 : bq2) + layer * NH;
    const float* w3 = (ph ? wp3 : wq3) + layer * NH;
    unsigned char* blob = g_blob[net];
    const int tid = threadIdx.x;

    for (int i = tid; i < BLOB_BYTES / 4; i += blockDim.x)
        reinterpret_cast<uint32_t*>(blob)[i] = 0u;
    __syncthreads();

    for (int idx = tid; idx < NH * NH; idx += blockDim.x) {
        int n = idx / NH, k = idx % NH;
        *reinterpret_cast<__nv_bfloat16*>(blob + n * SPB + 2 * k) = __float2bfloat16(W2[idx]);
    }
    for (int n = tid; n < NH; n += blockDim.x)
        *reinterpret_cast<__nv_bfloat16*>(blob + n * SPB + 208) = __float2bfloat16(b2[n]); // k=104
    for (int j = tid; j < NH; j += blockDim.x) {
        __nv_bfloat16* r = reinterpret_cast<__nv_bfloat16*>(blob + OB_W1H + 16 * j);
        r[0] = __float2bfloat16(W1[3 * j]);
        r[1] = __float2bfloat16(W1[3 * j + 1]);
        r[2] = __float2bfloat16(W1[3 * j + 2]);
        r[3] = __float2bfloat16(b1[j]);
        *reinterpret_cast<__nv_bfloat16*>(blob + OB_W1G + 2 * j)       = __float2bfloat16(W1[3 * j]);
        *reinterpret_cast<__nv_bfloat16*>(blob + OB_W1G + 240 + 2 * j) = __float2bfloat16(W1[3 * j + 1]);
    }
    for (int i = tid; i < 52; i += blockDim.x) {
        int n = 8 * (i >> 2) + 2 * (i & 3);
        uint32_t v = 0u;
        if (n + 1 < NH) {
            __nv_bfloat162 t = __floats2bfloat162_rn(w3[n], w3[n + 1]);
            v = *reinterpret_cast<uint32_t*>(&t);
        }
        reinterpret_cast<uint32_t*>(blob + OB_W3)[i] = v;
    }
}

// ------------------------------------------------------------------
__global__ __launch_bounds__(TPB, 2)
void sympnet_mma_kernel(const float* __restrict__ z, const float* __restrict__ tcol,
                        float* __restrict__ out)
{
    extern __shared__ unsigned char smem[];
    const uint32_t sbase = smem_u32(smem);

    const int tid = threadIdx.x;
    const int w = tid >> 5, l = tid & 31;
    const int el = l & 15;
    const int grow = blockIdx.x * TILEB + 16 * w + el;

    // prologue: prefetch pass-0 weights
    {
        const unsigned char* src = g_blob[0];
        for (int i = tid; i < REGA_BYTES / 16; i += TPB)
            cp16(sbase + SM_W2 + 16 * i, src + 16 * i);
        for (int i = tid; i < 3840 / 16; i += TPB)
            cp16(sbase + SM_W1G0 + 16 * i, src + OB_W1G + 16 * i);
        asm volatile("cp.async.commit_group;");
    }

    const float4 z4 = reinterpret_cast<const float4*>(z)[grow];
    float q0 = z4.x, q1 = z4.y, p0 = z4.z, p1 = z4.w;
    const float tval = tcol[grow];

    const uint32_t bW2  = sbase + SM_W2  + ((l & 7) + 8 * (l >> 4)) * SPB + 16 * ((l >> 3) & 1);
    const uint32_t bW2t = sbase + SM_W2  + ((l & 7) + 8 * ((l >> 3) & 1)) * SPB + 16 * (l >> 4);
    const uint32_t bW1h = sbase + SM_W1H + ((l & 7) + 8 * (l >> 3)) * 16;
    const uint32_t bW1gL = ((l & 7) + 8 * (l >> 4)) * 240 + 16 * ((l >> 3) & 1);
    const uint32_t sScr = sbase + SM_SCR + w * 6656 + l * 8;

    const uint32_t* w3pk = reinterpret_cast<const uint32_t*>(smem + SM_W3);
    const uint32_t biasA = ((l & 3) == 0) ? 0x00003F80u : 0u;   // bf16 1.0 at k=104
    const int r0 = l >> 2, r1 = r0 + 8;
    const float zc[4] = {0.f, 0.f, 0.f, 0.f};

#pragma unroll 1
    for (int pass = 0; pass < NPASS; ++pass) {
        const int ph = pass & 1;

        asm volatile("cp.async.wait_group 0;" ::: "memory");
        __syncthreads();

        const float x0 = ph ? p0 : q0;
        const float x1 = ph ? p1 : q1;

        float acc[2][NT][4];

        // ---- GEMM0: h1 for both branches ----
        {
            uint32_t bh[4][4];
#pragma unroll
            for (int g = 0; g < 4; ++g) ldsm4(bh[g], bW1h + g * 512);

            const float xa0 = __shfl_sync(0xffffffffu, x0, r0);
            const float xa1 = __shfl_sync(0xffffffffu, x1, r0);
            const float xb0 = __shfl_sync(0xffffffffu, x0, r1);
            const float xb1 = __shfl_sync(0xffffffffu, x1, r1);
            const float ta  = __shfl_sync(0xffffffffu, tval, r0);
            const float tb  = __shfl_sync(0xffffffffu, tval, r1);
#pragma unroll
            for (int mt = 0; mt < 2; ++mt) {
                uint32_t a0 = 0u, a1 = 0u;
                if ((l & 3) == 0)      { a0 = pack_bf2(xa0, xa1); a1 = pack_bf2(xb0, xb1); }
                else if ((l & 3) == 1) { a0 = pack_bf2(mt ? 0.f : ta, 1.f);
                                         a1 = pack_bf2(mt ? 0.f : tb, 1.f); }
#pragma unroll
                for (int nt = 0; nt < NT; ++nt)
                    mma16808i(acc[mt][nt], a0, a1, bh[nt >> 2][nt & 3], zc);
            }
        }

        // ---- sin(0) ----
        uint32_t spk0[NT][2], spk1[NT][2];
#pragma unroll
        for (int nt = 0; nt < NT; ++nt)
            sin_tile(acc[0][nt], spk0[nt], sScr + nt * 256);

        // ---- Phase A: GEMM1(0) || sin(1) ----
#pragma unroll
        for (int kt = 0; kt < KT; ++kt) {
            uint32_t b[NTP][4];
#pragma unroll
            for (int np = 0; np < NTP; ++np)
                ldsm4(b[np], bW2 + 32 * kt + np * 16 * SPB);
            uint32_t a[4];
            a[0] = spk0[2 * kt][0]; a[1] = spk0[2 * kt][1];
            a[2] = (kt < 6) ? spk0[2 * kt + 1][0] : biasA;
            a[3] = (kt < 6) ? spk0[2 * kt + 1][1] : biasA;
#pragma unroll
            for (int np = 0; np < NTP; ++np) {
                if (kt == 0) {
                    mma16816i(acc[0][2 * np], a, b[np][0], b[np][1], zc);
                    if (2 * np + 1 < NT) mma16816i(acc[0][2 * np + 1], a, b[np][2], b[np][3], zc);
                } else {
                    mma16816(acc[0][2 * np], a, b[np][0], b[np][1]);
                    if (2 * np + 1 < NT) mma16816(acc[0][2 * np + 1], a, b[np][2], b[np][3]);
                }
            }
            sin_tile(acc[1][2 * kt], spk1[2 * kt], sScr + (NT + 2 * kt) * 256);
            if (2 * kt + 1 < NT)
                sin_tile(acc[1][2 * kt + 1], spk1[2 * kt + 1], sScr + (NT + 2 * kt + 1) * 256);
        }

        // ---- Phase B: GEMM1(1) || stage3(0) ----
        uint32_t af0[KT][4];
#pragma unroll
        for (int kt = 0; kt < KT; ++kt) {
            uint32_t b[NTP][4];
#pragma unroll
            for (int np = 0; np < NTP; ++np)
                ldsm4(b[np], bW2 + 32 * kt + np * 16 * SPB);
            uint32_t a[4];
            a[0] = spk1[2 * kt][0]; a[1] = spk1[2 * kt][1];
            a[2] = (kt < 6) ? spk1[2 * kt + 1][0] : biasA;
            a[3] = (kt < 6) ? spk1[2 * kt + 1][1] : biasA;
#pragma unroll
            for (int np = 0; np < NTP; ++np) {
                if (kt == 0) {
                    mma16816i(acc[1][2 * np], a, b[np][0], b[np][1], zc);
                    if (2 * np + 1 < NT) mma16816i(acc[1][2 * np + 1], a, b[np][2], b[np][3], zc);
                } else {
                    mma16816(acc[1][2 * np], a, b[np][0], b[np][1]);
                    if (2 * np + 1 < NT) mma16816(acc[1][2 * np + 1], a, b[np][2], b[np][3]);
                }
            }
            g2_tile(acc[0][2 * kt], w3pk[4 * (2 * kt) + (l & 3)], &af0[kt][0]);
            if (2 * kt + 1 < NT)
                g2_tile(acc[0][2 * kt + 1], w3pk[4 * (2 * kt + 1) + (l & 3)], &af0[kt][2]);
            else { af0[kt][2] = 0u; af0[kt][3] = 0u; }
        }

        // ---- Phase C: GEMM2(0) || stage3(1) ----
        uint32_t af1[KT][4];
#pragma unroll
        for (int kt = 0; kt < KT; ++kt) {
            uint32_t b[NTP][4];
#pragma unroll
            for (int np = 0; np < NTP; ++np)
                ldsm4t(b[np], bW2t + 16 * kt * SPB + 32 * np);
#pragma unroll
            for (int np = 0; np < NTP; ++np) {
                if (kt == 0) {
                    mma16816i(acc[0][2 * np], af0[0], b[np][0], b[np][1], zc);
                    if (2 * np + 1 < NT) mma16816i(acc[0][2 * np + 1], af0[0], b[np][2], b[np][3], zc);
                } else {
                    mma16816(acc[0][2 * np], af0[kt], b[np][0], b[np][1]);
                    if (2 * np + 1 < NT) mma16816(acc[0][2 * np + 1], af0[kt], b[np][2], b[np][3]);
                }
            }
            g2_tile(acc[1][2 * kt], w3pk[4 * (2 * kt) + (l & 3)], &af1[kt][0]);
            if (2 * kt + 1 < NT)
                g2_tile(acc[1][2 * kt + 1], w3pk[4 * (2 * kt + 1) + (l & 3)], &af1[kt][2]);
            else { af1[kt][2] = 0u; af1[kt][3] = 0u; }
        }

        // ---- Phase D: GEMM2(1) || stage5(0) ----
        uint32_t af30[KT][4];
#pragma unroll
        for (int kt = 0; kt < KT; ++kt) {
            uint32_t b[NTP][4];
#pragma unroll
            for (int np = 0; np < NTP; ++np)
                ldsm4t(b[np], bW2t + 16 * kt * SPB + 32 * np);
#pragma unroll
            for (int np = 0; np < NTP; ++np) {
                if (kt == 0) {
                    mma16816i(acc[1][2 * np], af1[0], b[np][0], b[np][1], zc);
                    if (2 * np + 1 < NT) mma16816i(acc[1][2 * np + 1], af1[0], b[np][2], b[np][3], zc);
                } else {
                    mma16816(acc[1][2 * np], af1[kt], b[np][0], b[np][1]);
                    if (2 * np + 1 < NT) mma16816(acc[1][2 * np + 1], af1[kt], b[np][2], b[np][3]);
                }
            }
            g1_tile(acc[0][2 * kt], sScr + (2 * kt) * 256, &af30[kt][0]);
            if (2 * kt + 1 < NT)
                g1_tile(acc[0][2 * kt + 1], sScr + (2 * kt + 1) * 256, &af30[kt][2]);
            else { af30[kt][2] = 0u; af30[kt][3] = 0u; }
        }

        // ---- all warps done with W2/W1H/W3: prefetch next pass ----
        __syncthreads();
        if (pass + 1 < NPASS) {
            const unsigned char* src = g_blob[pass + 1];
            for (int i = tid; i < REGA_BYTES / 16; i += TPB)
                cp16(sbase + SM_W2 + 16 * i, src + 16 * i);
            const uint32_t dstG = sbase + (((pass + 1) & 1) ? SM_W1G1 : SM_W1G0);
            for (int i = tid; i < 3840 / 16; i += TPB)
                cp16(dstG + 16 * i, src + OB_W1G + 16 * i);
            asm volatile("cp.async.commit_group;");
        }

        // ---- Phase E: GEMM3(0) || stage5(1) ; then GEMM3(1) ----
        float acc3[2][4];
        const uint32_t bW1g = sbase + ((pass & 1) ? SM_W1G1 : SM_W1G0) + bW1gL;
#pragma unroll
        for (int kt = 0; kt < KT; ++kt) {
            uint32_t bg[4];
            ldsm4(bg, bW1g + 32 * kt);
            if (kt == 0) mma16816i(acc3[0], af30[0], bg[0], bg[1], zc);
            else         mma16816 (acc3[0], af30[kt], bg[0], bg[1]);
        }
        uint32_t af31[KT][4];
#pragma unroll
        for (int kt = 0; kt < KT; ++kt) {
            g1_tile(acc[1][2 * kt], sScr + (NT + 2 * kt) * 256, &af31[kt][0]);
            if (2 * kt + 1 < NT)
                g1_tile(acc[1][2 * kt + 1], sScr + (NT + 2 * kt + 1) * 256, &af31[kt][2]);
            else { af31[kt][2] = 0u; af31[kt][3] = 0u; }
        }
#pragma unroll
        for (int kt = 0; kt < KT; ++kt) {
            uint32_t bg[4];
            ldsm4(bg, bW1g + 32 * kt);
            if (kt == 0) mma16816i(acc3[1], af31[0], bg[0], bg[1], zc);
            else         mma16816 (acc3[1], af31[kt], bg[0], bg[1]);
        }

        // ---- gg = grad(t) - grad(0): register diff + intra-warp shuffles ----
        float d0 = acc3[0][0] - acc3[1][0];
        float d1 = acc3[0][1] - acc3[1][1];
        float d2 = acc3[0][2] - acc3[1][2];
        float d3 = acc3[0][3] - acc3[1][3];
        const int h = 4 * (el & 7);
        float s0 = __shfl_sync(0xffffffffu, d0, h);
        float s1 = __shfl_sync(0xffffffffu, d1, h);
        float s2 = __shfl_sync(0xffffffffu, d2, h);
        float s3 = __shfl_sync(0xffffffffu, d3, h);
        const float g0 = (el < 8) ? s0 : s2;
        const float g1 = (el < 8) ? s1 : s3;
        if (ph == 0) { p0 -= g0; p1 -= g1; }
        else         { q0 += g0; q1 += g1; }
    }

    if (l < 16)
        reinterpret_cast<float4*>(out)[grow] = make_float4(q0, q1, p0, p1);
}

// ------------------------------------------------------------------
extern "C" void kernel_launch(void* const* d_in, const int* in_sizes, int n_in,
                              void* d_out, int out_size)
{
    const float* z   = (const float*)d_in[0];
    const float* t   = (const float*)d_in[1];
    const float* Wq1 = (const float*)d_in[2];
    const float* bq1 = (const float*)d_in[3];
    const float* Wq2 = (const float*)d_in[4];
    const float* bq2 = (const float*)d_in[5];
    const float* wq3 = (const float*)d_in[6];
    const float* Wp1 = (const float*)d_in[7];
    const float* bp1 = (const float*)d_in[8];
    const float* Wp2 = (const float*)d_in[9];
    const float* bp2 = (const float*)d_in[10];
    const float* wp3 = (const float*)d_in[11];
    float* out = (float*)d_out;

    cudaFuncSetAttribute(sympnet_mma_kernel,
                         cudaFuncAttributeMaxDynamicSharedMemorySize, SM_TOTAL);

    prep_kernel<<<NPASS, 256>>>(Wq1, bq1, Wq2, bq2, wq3, Wp1, bp1, Wp2, bp2, wp3);
    sympnet_mma_kernel<<<NBATCH / TILEB, TPB, SM_TOTAL>>>(z, t, out);
}

// round 14
// speedup vs baseline: 1.7297x; 1.7297x over previous
#include <cuda_runtime.h>
#include <cuda_bf16.h>
#include <cstdint>

#define NBATCH 131072
#define NH   100
#define SP   120           // W2 tile pitch (bf16) = 240B, ldmatrix conflict-free
#define SPB  (SP * 2)
#define TPB  128
#define TILEB 64
#define NPASS 6
#define KT   7             // k16 tiles
#define NT   13            // n8 tiles (104 >= 100)
#define NTP  7

// ---- SMEM layout ----
#define SM_SCR   0                      // 4 warps x 26 slots x 32 lanes x 8B = 26624
#define SM_W2    26624                  // 112 x SP bf16 = 26880 (b2 folded in col 104)
#define SM_W1H   53504                  // 128 rows x 16B = 2048
#define SM_W3    55552                  // packed bf16x2 w3: 256
#define SM_W1G0  55808                  // 16 rows x 240B = 3840 (double buffered)
#define SM_W1G1  59648                  // 3840
#define SM_TOTAL 63488                  // -> 3 CTAs/SM

// ---- weight blob: [ W2 | W1H | W3pk ] (region A) + [ W1G ] (region B) ----
#define OB_W1H 26880
#define OB_W3  28928
#define REGA_BYTES 29184
#define OB_W1G 29184
#define BLOB_BYTES 33024

__device__ __align__(16) unsigned char g_blob[NPASS][BLOB_BYTES];

__device__ __forceinline__ uint32_t smem_u32(const void* p) {
    uint32_t a;
    asm("{ .reg .u64 t; cvta.to.shared.u64 t, %1; cvt.u32.u64 %0, t; }" : "=r"(a) : "l"(p));
    return a;
}
__device__ __forceinline__ void ldsm4(uint32_t* r, uint32_t addr) {
    asm volatile("ldmatrix.sync.aligned.m8n8.x4.shared.b16 {%0,%1,%2,%3}, [%4];"
                 : "=r"(r[0]), "=r"(r[1]), "=r"(r[2]), "=r"(r[3]) : "r"(addr));
}
__device__ __forceinline__ void ldsm4t(uint32_t* r, uint32_t addr) {
    asm volatile("ldmatrix.sync.aligned.m8n8.x4.trans.shared.b16 {%0,%1,%2,%3}, [%4];"
                 : "=r"(r[0]), "=r"(r[1]), "=r"(r[2]), "=r"(r[3]) : "r"(addr));
}
__device__ __forceinline__ void mma16816(float* d, const uint32_t* a, uint32_t b0, uint32_t b1) {
    asm volatile("mma.sync.aligned.m16n8k16.row.col.f32.bf16.bf16.f32 "
                 "{%0,%1,%2,%3}, {%4,%5,%6,%7}, {%8,%9}, {%0,%1,%2,%3};"
                 : "+f"(d[0]), "+f"(d[1]), "+f"(d[2]), "+f"(d[3])
                 : "r"(a[0]), "r"(a[1]), "r"(a[2]), "r"(a[3]), "r"(b0), "r"(b1));
}
__device__ __forceinline__ void mma16816i(float* d, const uint32_t* a, uint32_t b0, uint32_t b1,
                                          const float* c) {
    asm volatile("mma.sync.aligned.m16n8k16.row.col.f32.bf16.bf16.f32 "
                 "{%0,%1,%2,%3}, {%4,%5,%6,%7}, {%8,%9}, {%10,%11,%12,%13};"
                 : "=f"(d[0]), "=f"(d[1]), "=f"(d[2]), "=f"(d[3])
                 : "r"(a[0]), "r"(a[1]), "r"(a[2]), "r"(a[3]), "r"(b0), "r"(b1),
                   "f"(c[0]), "f"(c[1]), "f"(c[2]), "f"(c[3]));
}
__device__ __forceinline__ void mma16808i(float* d, uint32_t a0, uint32_t a1, uint32_t b0,
                                          const float* c) {
    asm volatile("mma.sync.aligned.m16n8k8.row.col.f32.bf16.bf16.f32 "
                 "{%0,%1,%2,%3}, {%4,%5}, {%6}, {%7,%8,%9,%10};"
                 : "=f"(d[0]), "=f"(d[1]), "=f"(d[2]), "=f"(d[3])
                 : "r"(a0), "r"(a1), "r"(b0),
                   "f"(c[0]), "f"(c[1]), "f"(c[2]), "f"(c[3]));
}
__device__ __forceinline__ void cp16(uint32_t smem_dst, const void* gsrc) {
    asm volatile("cp.async.cg.shared.global [%0], [%1], 16;"
                 :: "r"(smem_dst), "l"(gsrc));
}
__device__ __forceinline__ uint32_t pack_bf2(float a, float b) {
    __nv_bfloat162 t = __floats2bfloat162_rn(a, b);
    return *reinterpret_cast<uint32_t*>(&t);
}
__device__ __forceinline__ uint32_t hmul2u(uint32_t a, uint32_t b) {
    __nv_bfloat162 r = __hmul2(*reinterpret_cast<__nv_bfloat162*>(&a),
                               *reinterpret_cast<__nv_bfloat162*>(&b));
    return *reinterpret_cast<uint32_t*>(&r);
}
__device__ __forceinline__ uint32_t hfma2u(uint32_t a, uint32_t b, uint32_t c) {
    __nv_bfloat162 r = __hfma2(*reinterpret_cast<__nv_bfloat162*>(&a),
                               *reinterpret_cast<__nv_bfloat162*>(&b),
                               *reinterpret_cast<__nv_bfloat162*>(&c));
    return *reinterpret_cast<uint32_t*>(&r);
}
__device__ __forceinline__ uint32_t hsub2u(uint32_t a, uint32_t b) {
    __nv_bfloat162 r = __hsub2(*reinterpret_cast<__nv_bfloat162*>(&a),
                               *reinterpret_cast<__nv_bfloat162*>(&b));
    return *reinterpret_cast<uint32_t*>(&r);
}
#define NEGH2 0xBF00BF00u   // bf16x2 {-0.5,-0.5}
#define ONE2  0x3F803F80u   // bf16x2 {1,1}
#define M6TH  0xBE2BBE2Bu   // bf16x2 {-1/6,-1/6}

// s = h(1 - h^2/6) in packed bf16x2; store to warp-private scratch
__device__ __forceinline__ void sin_tile(const float* a4, uint32_t* s2, uint32_t scr) {
    uint32_t h01 = pack_bf2(a4[0], a4[1]);
    uint32_t h23 = pack_bf2(a4[2], a4[3]);
    s2[0] = hmul2u(h01, hfma2u(hmul2u(h01, h01), M6TH, ONE2));
    s2[1] = hmul2u(h23, hfma2u(hmul2u(h23, h23), M6TH, ONE2));
    asm volatile("st.shared.v2.u32 [%0], {%1,%2};" :: "r"(scr), "r"(s2[0]), "r"(s2[1]));
}
// g2 = (1 - h^2/2) * w3
__device__ __forceinline__ void g2_tile(const float* a4, uint32_t wpk, uint32_t* o2) {
    uint32_t h01 = pack_bf2(a4[0], a4[1]);
    uint32_t h23 = pack_bf2(a4[2], a4[3]);
    o2[0] = hmul2u(hfma2u(hmul2u(h01, h01), NEGH2, ONE2), wpk);
    o2[1] = hmul2u(hfma2u(hmul2u(h23, h23), NEGH2, ONE2), wpk);
}
// g1 = gc * (1 - s^2/2), s from scratch
__device__ __forceinline__ void g1_tile(const float* a4, uint32_t scr, uint32_t* o2) {
    uint32_t u01, u23;
    asm("ld.shared.v2.u32 {%0,%1}, [%2];" : "=r"(u01), "=r"(u23) : "r"(scr));
    uint32_t c01 = hfma2u(hmul2u(u01, u01), NEGH2, ONE2);
    uint32_t c23 = hfma2u(hmul2u(u23, u23), NEGH2, ONE2);
    o2[0] = hmul2u(pack_bf2(a4[0], a4[1]), c01);
    o2[1] = hmul2u(pack_bf2(a4[2], a4[3]), c23);
}

// ------------------------------------------------------------------
__global__ void prep_kernel(
    const float* __restrict__ Wq1, const float* __restrict__ bq1,
    const float* __restrict__ Wq2, const float* __restrict__ bq2,
    const float* __restrict__ wq3,
    const float* __restrict__ Wp1, const float* __restrict__ bp1,
    const float* __restrict__ Wp2, const float* __restrict__ bp2,
    const float* __restrict__ wp3)
{
    const int net = blockIdx.x, layer = net >> 1, ph = net & 1;
    const float* W1 = (ph ? Wp1 : Wq1) + layer * NH * 3;
    const float* b1 = (ph ? bp1 : bq1) + layer * NH;
    const float* W2 = (ph ? Wp2 : Wq2) + layer * NH * NH;
    const float* b2 = (ph ? bp2 : bq2) + layer * NH;
    const float* w3 = (ph ? wp3 : wq3) + layer * NH;
    unsigned char* blob = g_blob[net];
    const int tid = threadIdx.x;

    for (int i = tid; i < BLOB_BYTES / 4; i += blockDim.x)
        reinterpret_cast<uint32_t*>(blob)[i] = 0u;
    __syncthreads();

    for (int idx = tid; idx < NH * NH; idx += blockDim.x) {
        int n = idx / NH, k = idx % NH;
        *reinterpret_cast<__nv_bfloat16*>(blob + n * SPB + 2 * k) = __float2bfloat16(W2[idx]);
    }
    for (int n = tid; n < NH; n += blockDim.x)
        *reinterpret_cast<__nv_bfloat16*>(blob + n * SPB + 208) = __float2bfloat16(b2[n]); // k=104
    for (int j = tid; j < NH; j += blockDim.x) {
        __nv_bfloat16* r = reinterpret_cast<__nv_bfloat16*>(blob + OB_W1H + 16 * j);
        r[0] = __float2bfloat16(W1[3 * j]);
        r[1] = __float2bfloat16(W1[3 * j + 1]);
        r[2] = __float2bfloat16(W1[3 * j + 2]);
        r[3] = __float2bfloat16(b1[j]);
        *reinterpret_cast<__nv_bfloat16*>(blob + OB_W1G + 2 * j)       = __float2bfloat16(W1[3 * j]);
        *reinterpret_cast<__nv_bfloat16*>(blob + OB_W1G + 240 + 2 * j) = __float2bfloat16(W1[3 * j + 1]);
    }
    for (int i = tid; i < 52; i += blockDim.x) {
        int n = 8 * (i >> 2) + 2 * (i & 3);
        uint32_t v = 0u;
        if (n + 1 < NH) {
            __nv_bfloat162 t = __floats2bfloat162_rn(w3[n], w3[n + 1]);
            v = *reinterpret_cast<uint32_t*>(&t);
        }
        reinterpret_cast<uint32_t*>(blob + OB_W3)[i] = v;
    }
}

// ------------------------------------------------------------------
__global__ __launch_bounds__(TPB, 3)
void sympnet_mma_kernel(const float* __restrict__ z, const float* __restrict__ tcol,
                        float* __restrict__ out)
{
    extern __shared__ unsigned char smem[];
    const uint32_t sbase = smem_u32(smem);

    const int tid = threadIdx.x;
    const int w = tid >> 5, l = tid & 31;
    const int el = l & 15;               // batch element within warp (lanes 16-31 duplicate)
    const int grow = blockIdx.x * TILEB + 16 * w + el;

    // prologue: prefetch pass-0 weights
    {
        const unsigned char* src = g_blob[0];
        for (int i = tid; i < REGA_BYTES / 16; i += TPB)
            cp16(sbase + SM_W2 + 16 * i, src + 16 * i);
        for (int i = tid; i < 3840 / 16; i += TPB)
            cp16(sbase + SM_W1G0 + 16 * i, src + OB_W1G + 16 * i);
        asm volatile("cp.async.commit_group;");
    }

    const float4 z4 = reinterpret_cast<const float4*>(z)[grow];
    float q0 = z4.x, q1 = z4.y, p0 = z4.z, p1 = z4.w;
    const float tval = tcol[grow];

    const uint32_t bW2  = sbase + SM_W2  + ((l & 7) + 8 * (l >> 4)) * SPB + 16 * ((l >> 3) & 1);
    const uint32_t bW2t = sbase + SM_W2  + ((l & 7) + 8 * ((l >> 3) & 1)) * SPB + 16 * (l >> 4);
    const uint32_t bW1h = sbase + SM_W1H + ((l & 7) + 8 * (l >> 3)) * 16;
    const uint32_t bW1gL = ((l & 7) + 8 * (l >> 4)) * 240 + 16 * ((l >> 3) & 1);
    const uint32_t sScr = sbase + SM_SCR + w * 6656 + l * 8;

    const uint32_t* w3pk = reinterpret_cast<const uint32_t*>(smem + SM_W3);
    const uint32_t biasA = ((l & 3) == 0) ? 0x00003F80u : 0u;   // bf16 1.0 at k=104
    const int r0 = l >> 2, r1 = r0 + 8;
    const float zc[4] = {0.f, 0.f, 0.f, 0.f};

#pragma unroll 1
    for (int pass = 0; pass < NPASS; ++pass) {
        const int ph = pass & 1;

        asm volatile("cp.async.wait_group 0;" ::: "memory");
        __syncthreads();   // this pass's weights visible; prior reads complete

        const float x0 = ph ? p0 : q0;
        const float x1 = ph ? p1 : q1;

        // ---- GEMM0 (fused sin): h1 -> s per tile, both branches ----
        uint32_t spk[2][NT][2];
        {
            uint32_t bh[4][4];
#pragma unroll
            for (int g = 0; g < 4; ++g) ldsm4(bh[g], bW1h + g * 512);

            const float xa0 = __shfl_sync(0xffffffffu, x0, r0);
            const float xa1 = __shfl_sync(0xffffffffu, x1, r0);
            const float xb0 = __shfl_sync(0xffffffffu, x0, r1);
            const float xb1 = __shfl_sync(0xffffffffu, x1, r1);
            const float ta  = __shfl_sync(0xffffffffu, tval, r0);
            const float tb  = __shfl_sync(0xffffffffu, tval, r1);

            uint32_t aF[2][2];
#pragma unroll
            for (int mt = 0; mt < 2; ++mt) {
                aF[mt][0] = 0u; aF[mt][1] = 0u;
                if ((l & 3) == 0)      { aF[mt][0] = pack_bf2(xa0, xa1);
                                         aF[mt][1] = pack_bf2(xb0, xb1); }
                else if ((l & 3) == 1) { aF[mt][0] = pack_bf2(mt ? 0.f : ta, 1.f);
                                         aF[mt][1] = pack_bf2(mt ? 0.f : tb, 1.f); }
            }
#pragma unroll
            for (int nt = 0; nt < NT; ++nt) {
                float h0[4], h1v[4];
                mma16808i(h0,  aF[0][0], aF[0][1], bh[nt >> 2][nt & 3], zc);
                mma16808i(h1v, aF[1][0], aF[1][1], bh[nt >> 2][nt & 3], zc);
                sin_tile(h0,  spk[0][nt], sScr + nt * 256);
                sin_tile(h1v, spk[1][nt], sScr + (NT + nt) * 256);
            }
        }

        // ---- GEMM1: H2 = S @ W2^T (+b2 via k=104 one-column), kt-outer ----
        float acc[2][NT][4];
#pragma unroll
        for (int kt = 0; kt < KT; ++kt) {
            uint32_t b[NTP][4];
#pragma unroll
            for (int np = 0; np < NTP; ++np)
                ldsm4(b[np], bW2 + 32 * kt + np * 16 * SPB);
#pragma unroll
            for (int mt = 0; mt < 2; ++mt) {
                uint32_t a[4];
                a[0] = spk[mt][2 * kt][0];
                a[1] = spk[mt][2 * kt][1];
                a[2] = (kt < 6) ? spk[mt][2 * kt + 1][0] : biasA;
                a[3] = (kt < 6) ? spk[mt][2 * kt + 1][1] : biasA;
#pragma unroll
                for (int np = 0; np < NTP; ++np) {
                    if (kt == 0) {
                        mma16816i(acc[mt][2 * np], a, b[np][0], b[np][1], zc);
                        if (2 * np + 1 < NT)
                            mma16816i(acc[mt][2 * np + 1], a, b[np][2], b[np][3], zc);
                    } else {
                        mma16816(acc[mt][2 * np], a, b[np][0], b[np][1]);
                        if (2 * np + 1 < NT)
                            mma16816(acc[mt][2 * np + 1], a, b[np][2], b[np][3]);
                    }
                }
            }
        }

        // ---- stage3: g2 = (1 - h2^2/2) * w3 -> GEMM2 A-fragments ----
        uint32_t af[2][KT][4];
#pragma unroll
        for (int nt = 0; nt < NT; ++nt) {
            const uint32_t wpk = w3pk[4 * nt + (l & 3)];
#pragma unroll
            for (int mt = 0; mt < 2; ++mt) {
                g2_tile(acc[mt][nt], wpk, &af[mt][nt >> 1][2 * (nt & 1)]);
            }
        }
#pragma unroll
        for (int mt = 0; mt < 2; ++mt) { af[mt][6][2] = 0u; af[mt][6][3] = 0u; }

        // ---- GEMM2 (np-outer, fused stage5 + branch diff) ----
        uint32_t dA[KT][4];
#pragma unroll
        for (int np = 0; np < NTP; ++np) {
            uint32_t b[KT][4];
#pragma unroll
            for (int kt = 0; kt < KT; ++kt)
                ldsm4t(b[kt], bW2t + 16 * kt * SPB + 32 * np);

            float a2[2][2][4];
#pragma unroll
            for (int mt = 0; mt < 2; ++mt) {
#pragma unroll
                for (int kt = 0; kt < KT; ++kt) {
                    if (kt == 0) {
                        mma16816i(a2[mt][0], af[mt][0], b[0][0], b[0][1], zc);
                        if (2 * np + 1 < NT)
                            mma16816i(a2[mt][1], af[mt][0], b[0][2], b[0][3], zc);
                    } else {
                        mma16816(a2[mt][0], af[mt][kt], b[kt][0], b[kt][1]);
                        if (2 * np + 1 < NT)
                            mma16816(a2[mt][1], af[mt][kt], b[kt][2], b[kt][3]);
                    }
                }
            }
            // stage5 + diff for tiles nt = 2np (+1)
#pragma unroll
            for (int sub = 0; sub < 2; ++sub) {
                if (2 * np + sub < NT) {
                    const int nt = 2 * np + sub;
                    uint32_t o0[2], o1[2];
                    g1_tile(a2[0][sub], sScr + nt * 256, o0);
                    g1_tile(a2[1][sub], sScr + (NT + nt) * 256, o1);
                    dA[np][2 * sub]     = hsub2u(o0[0], o1[0]);
                    dA[np][2 * sub + 1] = hsub2u(o0[1], o1[1]);
                } else {
                    dA[np][2 * sub] = 0u; dA[np][2 * sub + 1] = 0u;
                }
            }
        }

        // ---- all warps done with W2/W1H/W3: prefetch next pass ----
        __syncthreads();
        if (pass + 1 < NPASS) {
            const unsigned char* src = g_blob[pass + 1];
            for (int i = tid; i < REGA_BYTES / 16; i += TPB)
                cp16(sbase + SM_W2 + 16 * i, src + 16 * i);
            const uint32_t dstG = sbase + (((pass + 1) & 1) ? SM_W1G1 : SM_W1G0);
            for (int i = tid; i < 3840 / 16; i += TPB)
                cp16(dstG + 16 * i, src + OB_W1G + 16 * i);
            asm volatile("cp.async.commit_group;");
        }

        // ---- GEMM3: gg = (G1(t)-G1(0)) @ W1[:, :2], single GEMM ----
        float acc3[4];
        {
            const uint32_t bW1g = sbase + ((pass & 1) ? SM_W1G1 : SM_W1G0) + bW1gL;
#pragma unroll
            for (int kt = 0; kt < KT; ++kt) {
                uint32_t bg[4];
                ldsm4(bg, bW1g + 32 * kt);
                if (kt == 0) mma16816i(acc3, dA[0], bg[0], bg[1], zc);
                else         mma16816 (acc3, dA[kt], bg[0], bg[1]);
            }
        }

        // ---- broadcast gg within warp, update state ----
        const int h = 4 * (el & 7);
        float s0 = __shfl_sync(0xffffffffu, acc3[0], h);
        float s1 = __shfl_sync(0xffffffffu, acc3[1], h);
        float s2 = __shfl_sync(0xffffffffu, acc3[2], h);
        float s3 = __shfl_sync(0xffffffffu, acc3[3], h);
        const float g0 = (el < 8) ? s0 : s2;
        const float g1 = (el < 8) ? s1 : s3;
        if (ph == 0) { p0 -= g0; p1 -= g1; }
        else         { q0 += g0; q1 += g1; }
    }

    if (l < 16)
        reinterpret_cast<float4*>(out)[grow] = make_float4(q0, q1, p0, p1);
}

// ------------------------------------------------------------------
extern "C" void kernel_launch(void* const* d_in, const int* in_sizes, int n_in,
                              void* d_out, int out_size)
{
    const float* z   = (const float*)d_in[0];
    const float* t   = (const float*)d_in[1];
    const float* Wq1 = (const float*)d_in[2];
    const float* bq1 = (const float*)d_in[3];
    const float* Wq2 = (const float*)d_in[4];
    const float* bq2 = (const float*)d_in[5];
    const float* wq3 = (const float*)d_in[6];
    const float* Wp1 = (const float*)d_in[7];
    const float* bp1 = (const float*)d_in[8];
    const float* Wp2 = (const float*)d_in[9];
    const float* bp2 = (const float*)d_in[10];
    const float* wp3 = (const float*)d_in[11];
    float* out = (float*)d_out;

    cudaFuncSetAttribute(sympnet_mma_kernel,
                         cudaFuncAttributeMaxDynamicSharedMemorySize, SM_TOTAL);

    prep_kernel<<<NPASS, 256>>>(Wq1, bq1, Wq2, bq2, wq3, Wp1, bp1, Wp2, bp2, wp3);
    sympnet_mma_kernel<<<NBATCH / TILEB, TPB, SM_TOTAL>>>(z, t, out);
}

// round 15
// speedup vs baseline: 1.7871x; 1.0332x over previous
#include <cuda_runtime.h>
#include <cuda_bf16.h>
#include <cstdint>

#define NBATCH 131072
#define NH   100
#define SP   120           // W2 tile pitch (bf16) = 240B, ldmatrix conflict-free
#define SPB  (SP * 2)
#define TPB  128
#define TILEB 64
#define NPASS 6
#define KT   7             // k16 tiles
#define NT   13            // n8 tiles (104 >= 100)
#define NTP  7

// ---- SMEM layout ----
#define SM_SCR   0                      // 4 warps x 26 slots x 32 lanes x 8B = 26624
#define SM_W2    26624                  // 112 x SP bf16 = 26880 (b2 folded in col 104)
#define SM_W1H   53504                  // 128 rows x 16B = 2048
#define SM_W3    55552                  // packed bf16x2 w3: 256
#define SM_W1G0  55808                  // 16 rows x 240B = 3840 (double buffered)
#define SM_W1G1  59648                  // 3840
#define SM_TOTAL 63488                  // -> 3 CTAs/SM

// ---- weight blob: [ W2 | W1H | W3pk ] (region A) + [ W1G ] (region B) ----
#define OB_W1H 26880
#define OB_W3  28928
#define REGA_BYTES 29184
#define OB_W1G 29184
#define BLOB_BYTES 33024

__device__ __align__(16) unsigned char g_blob[NPASS][BLOB_BYTES];

__device__ __forceinline__ uint32_t smem_u32(const void* p) {
    uint32_t a;
    asm("{ .reg .u64 t; cvta.to.shared.u64 t, %1; cvt.u32.u64 %0, t; }" : "=r"(a) : "l"(p));
    return a;
}
__device__ __forceinline__ void ldsm4(uint32_t* r, uint32_t addr) {
    asm volatile("ldmatrix.sync.aligned.m8n8.x4.shared.b16 {%0,%1,%2,%3}, [%4];"
                 : "=r"(r[0]), "=r"(r[1]), "=r"(r[2]), "=r"(r[3]) : "r"(addr));
}
__device__ __forceinline__ void ldsm4t(uint32_t* r, uint32_t addr) {
    asm volatile("ldmatrix.sync.aligned.m8n8.x4.trans.shared.b16 {%0,%1,%2,%3}, [%4];"
                 : "=r"(r[0]), "=r"(r[1]), "=r"(r[2]), "=r"(r[3]) : "r"(addr));
}
__device__ __forceinline__ void mma16816(float* d, const uint32_t* a, uint32_t b0, uint32_t b1) {
    asm volatile("mma.sync.aligned.m16n8k16.row.col.f32.bf16.bf16.f32 "
                 "{%0,%1,%2,%3}, {%4,%5,%6,%7}, {%8,%9}, {%0,%1,%2,%3};"
                 : "+f"(d[0]), "+f"(d[1]), "+f"(d[2]), "+f"(d[3])
                 : "r"(a[0]), "r"(a[1]), "r"(a[2]), "r"(a[3]), "r"(b0), "r"(b1));
}
__device__ __forceinline__ void mma16816i(float* d, const uint32_t* a, uint32_t b0, uint32_t b1,
                                          const float* c) {
    asm volatile("mma.sync.aligned.m16n8k16.row.col.f32.bf16.bf16.f32 "
                 "{%0,%1,%2,%3}, {%4,%5,%6,%7}, {%8,%9}, {%10,%11,%12,%13};"
                 : "=f"(d[0]), "=f"(d[1]), "=f"(d[2]), "=f"(d[3])
                 : "r"(a[0]), "r"(a[1]), "r"(a[2]), "r"(a[3]), "r"(b0), "r"(b1),
                   "f"(c[0]), "f"(c[1]), "f"(c[2]), "f"(c[3]));
}
__device__ __forceinline__ void mma16808i(float* d, uint32_t a0, uint32_t a1, uint32_t b0,
                                          const float* c) {
    asm volatile("mma.sync.aligned.m16n8k8.row.col.f32.bf16.bf16.f32 "
                 "{%0,%1,%2,%3}, {%4,%5}, {%6}, {%7,%8,%9,%10};"
                 : "=f"(d[0]), "=f"(d[1]), "=f"(d[2]), "=f"(d[3])
                 : "r"(a0), "r"(a1), "r"(b0),
                   "f"(c[0]), "f"(c[1]), "f"(c[2]), "f"(c[3]));
}
__device__ __forceinline__ void cp16(uint32_t smem_dst, const void* gsrc) {
    asm volatile("cp.async.cg.shared.global [%0], [%1], 16;"
                 :: "r"(smem_dst), "l"(gsrc));
}
__device__ __forceinline__ uint32_t pack_bf2(float a, float b) {
    __nv_bfloat162 t = __floats2bfloat162_rn(a, b);
    return *reinterpret_cast<uint32_t*>(&t);
}
__device__ __forceinline__ uint32_t hmul2u(uint32_t a, uint32_t b) {
    __nv_bfloat162 r = __hmul2(*reinterpret_cast<__nv_bfloat162*>(&a),
                               *reinterpret_cast<__nv_bfloat162*>(&b));
    return *reinterpret_cast<uint32_t*>(&r);
}
__device__ __forceinline__ uint32_t hfma2u(uint32_t a, uint32_t b, uint32_t c) {
    __nv_bfloat162 r = __hfma2(*reinterpret_cast<__nv_bfloat162*>(&a),
                               *reinterpret_cast<__nv_bfloat162*>(&b),
                               *reinterpret_cast<__nv_bfloat162*>(&c));
    return *reinterpret_cast<uint32_t*>(&r);
}
__device__ __forceinline__ uint32_t hsub2u(uint32_t a, uint32_t b) {
    __nv_bfloat162 r = __hsub2(*reinterpret_cast<__nv_bfloat162*>(&a),
                               *reinterpret_cast<__nv_bfloat162*>(&b));
    return *reinterpret_cast<uint32_t*>(&r);
}
#define NEGH2 0xBF00BF00u   // bf16x2 {-0.5,-0.5}
#define ONE2  0x3F803F80u   // bf16x2 {1,1}
#define M6TH  0xBE2BBE2Bu   // bf16x2 {-1/6,-1/6}

// s = h(1 - h^2/6) in packed bf16x2; store to warp-private scratch
__device__ __forceinline__ void sin_tile(const float* a4, uint32_t* s2, uint32_t scr) {
    uint32_t h01 = pack_bf2(a4[0], a4[1]);
    uint32_t h23 = pack_bf2(a4[2], a4[3]);
    s2[0] = hmul2u(h01, hfma2u(hmul2u(h01, h01), M6TH, ONE2));
    s2[1] = hmul2u(h23, hfma2u(hmul2u(h23, h23), M6TH, ONE2));
    asm volatile("st.shared.v2.u32 [%0], {%1,%2};" :: "r"(scr), "r"(s2[0]), "r"(s2[1]));
}
// g2 = (1 - h^2/2) * w3
__device__ __forceinline__ void g2_tile(const float* a4, uint32_t wpk, uint32_t* o2) {
    uint32_t h01 = pack_bf2(a4[0], a4[1]);
    uint32_t h23 = pack_bf2(a4[2], a4[3]);
    o2[0] = hmul2u(hfma2u(hmul2u(h01, h01), NEGH2, ONE2), wpk);
    o2[1] = hmul2u(hfma2u(hmul2u(h23, h23), NEGH2, ONE2), wpk);
}
// g1 = gc * (1 - s^2/2), s from scratch
__device__ __forceinline__ void g1_tile(const float* a4, uint32_t scr, uint32_t* o2) {
    uint32_t u01, u23;
    asm("ld.shared.v2.u32 {%0,%1}, [%2];" : "=r"(u01), "=r"(u23) : "r"(scr));
    uint32_t c01 = hfma2u(hmul2u(u01, u01), NEGH2, ONE2);
    uint32_t c23 = hfma2u(hmul2u(u23, u23), NEGH2, ONE2);
    o2[0] = hmul2u(pack_bf2(a4[0], a4[1]), c01);
    o2[1] = hmul2u(pack_bf2(a4[2], a4[3]), c23);
}

// ------------------------------------------------------------------
__global__ void prep_kernel(
    const float* __restrict__ Wq1, const float* __restrict__ bq1,
    const float* __restrict__ Wq2, const float* __restrict__ bq2,
    const float* __restrict__ wq3,
    const float* __restrict__ Wp1, const float* __restrict__ bp1,
    const float* __restrict__ Wp2, const float* __restrict__ bp2,
    const float* __restrict__ wp3)
{
    const int net = blockIdx.x, layer = net >> 1, ph = net & 1;
    const float* W1 = (ph ? Wp1 : Wq1) + layer * NH * 3;
    const float* b1 = (ph ? bp1 : bq1) + layer * NH;
    const float* W2 = (ph ? Wp2 : Wq2) + layer * NH * NH;
    const float* b2 = (ph ? bp2 : bq2) + layer * NH;
    const float* w3 = (ph ? wp3 : wq3) + layer * NH;
    unsigned char* blob = g_blob[net];
    const int tid = threadIdx.x;

    for (int i = tid; i < BLOB_BYTES / 4; i += blockDim.x)
        reinterpret_cast<uint32_t*>(blob)[i] = 0u;
    __syncthreads();

    for (int idx = tid; idx < NH * NH; idx += blockDim.x) {
        int n = idx / NH, k = idx % NH;
        *reinterpret_cast<__nv_bfloat16*>(blob + n * SPB + 2 * k) = __float2bfloat16(W2[idx]);
    }
    for (int n = tid; n < NH; n += blockDim.x)
        *reinterpret_cast<__nv_bfloat16*>(blob + n * SPB + 208) = __float2bfloat16(b2[n]); // k=104
    for (int j = tid; j < NH; j += blockDim.x) {
        __nv_bfloat16* r = reinterpret_cast<__nv_bfloat16*>(blob + OB_W1H + 16 * j);
        r[0] = __float2bfloat16(W1[3 * j]);
        r[1] = __float2bfloat16(W1[3 * j + 1]);
        r[2] = __float2bfloat16(W1[3 * j + 2]);
        r[3] = __float2bfloat16(b1[j]);
        *reinterpret_cast<__nv_bfloat16*>(blob + OB_W1G + 2 * j)       = __float2bfloat16(W1[3 * j]);
        *reinterpret_cast<__nv_bfloat16*>(blob + OB_W1G + 240 + 2 * j) = __float2bfloat16(W1[3 * j + 1]);
    }
    for (int i = tid; i < 52; i += blockDim.x) {
        int n = 8 * (i >> 2) + 2 * (i & 3);
        uint32_t v = 0u;
        if (n + 1 < NH) {
            __nv_bfloat162 t = __floats2bfloat162_rn(w3[n], w3[n + 1]);
            v = *reinterpret_cast<uint32_t*>(&t);
        }
        reinterpret_cast<uint32_t*>(blob + OB_W3)[i] = v;
    }
}

// ------------------------------------------------------------------
__global__ __launch_bounds__(TPB, 3)
void sympnet_mma_kernel(const float* __restrict__ z, const float* __restrict__ tcol,
                        float* __restrict__ out)
{
    extern __shared__ unsigned char smem[];
    const uint32_t sbase = smem_u32(smem);

    const int tid = threadIdx.x;
    const int w = tid >> 5, l = tid & 31;
    const int el = l & 15;               // batch element within warp (lanes 16-31 duplicate)
    const int grow = blockIdx.x * TILEB + 16 * w + el;

    // prologue: prefetch pass-0 weights
    {
        const unsigned char* src = g_blob[0];
        for (int i = tid; i < REGA_BYTES / 16; i += TPB)
            cp16(sbase + SM_W2 + 16 * i, src + 16 * i);
        for (int i = tid; i < 3840 / 16; i += TPB)
            cp16(sbase + SM_W1G0 + 16 * i, src + OB_W1G + 16 * i);
        asm volatile("cp.async.commit_group;");
    }

    const float4 z4 = reinterpret_cast<const float4*>(z)[grow];
    float q0 = z4.x, q1 = z4.y, p0 = z4.z, p1 = z4.w;
    const float tval = tcol[grow];

    const uint32_t bW2  = sbase + SM_W2  + ((l & 7) + 8 * (l >> 4)) * SPB + 16 * ((l >> 3) & 1);
    const uint32_t bW2t = sbase + SM_W2  + ((l & 7) + 8 * ((l >> 3) & 1)) * SPB + 16 * (l >> 4);
    const uint32_t bW1h = sbase + SM_W1H + ((l & 7) + 8 * (l >> 3)) * 16;
    const uint32_t bW1gL = ((l & 7) + 8 * (l >> 4)) * 240 + 16 * ((l >> 3) & 1);
    const uint32_t sScr = sbase + SM_SCR + w * 6656 + l * 8;

    const uint32_t* w3pk = reinterpret_cast<const uint32_t*>(smem + SM_W3);
    const uint32_t biasA = ((l & 3) == 0) ? 0x00003F80u : 0u;   // bf16 1.0 at k=104
    const int r0 = l >> 2, r1 = r0 + 8;
    const float zc[4] = {0.f, 0.f, 0.f, 0.f};

#pragma unroll 1
    for (int pass = 0; pass < NPASS; ++pass) {
        const int ph = pass & 1;

        asm volatile("cp.async.wait_group 0;" ::: "memory");
        __syncthreads();   // this pass's weights visible; prior reads complete

        const float x0 = ph ? p0 : q0;
        const float x1 = ph ? p1 : q1;

        // ---- GEMM0 (fused sin): h1 -> s per tile, both branches ----
        uint32_t spk[2][NT][2];
        {
            uint32_t bh[4][4];
#pragma unroll
            for (int g = 0; g < 4; ++g) ldsm4(bh[g], bW1h + g * 512);

            const float xa0 = __shfl_sync(0xffffffffu, x0, r0);
            const float xa1 = __shfl_sync(0xffffffffu, x1, r0);
            const float xb0 = __shfl_sync(0xffffffffu, x0, r1);
            const float xb1 = __shfl_sync(0xffffffffu, x1, r1);
            const float ta  = __shfl_sync(0xffffffffu, tval, r0);
            const float tb  = __shfl_sync(0xffffffffu, tval, r1);

            uint32_t aF[2][2];
#pragma unroll
            for (int mt = 0; mt < 2; ++mt) {
                aF[mt][0] = 0u; aF[mt][1] = 0u;
                if ((l & 3) == 0)      { aF[mt][0] = pack_bf2(xa0, xa1);
                                         aF[mt][1] = pack_bf2(xb0, xb1); }
                else if ((l & 3) == 1) { aF[mt][0] = pack_bf2(mt ? 0.f : ta, 1.f);
                                         aF[mt][1] = pack_bf2(mt ? 0.f : tb, 1.f); }
            }
#pragma unroll
            for (int nt = 0; nt < NT; ++nt) {
                float h0[4], h1v[4];
                mma16808i(h0,  aF[0][0], aF[0][1], bh[nt >> 2][nt & 3], zc);
                mma16808i(h1v, aF[1][0], aF[1][1], bh[nt >> 2][nt & 3], zc);
                sin_tile(h0,  spk[0][nt], sScr + nt * 256);
                sin_tile(h1v, spk[1][nt], sScr + (NT + nt) * 256);
            }
        }

        // ---- GEMM1: H2 = S @ W2^T (+b2 via k=104 one-column), kt-outer ----
        float acc[2][NT][4];
#pragma unroll
        for (int kt = 0; kt < KT; ++kt) {
            uint32_t b[NTP][4];
#pragma unroll
            for (int np = 0; np < NTP; ++np)
                ldsm4(b[np], bW2 + 32 * kt + np * 16 * SPB);
#pragma unroll
            for (int mt = 0; mt < 2; ++mt) {
                uint32_t a[4];
                a[0] = spk[mt][2 * kt][0];
                a[1] = spk[mt][2 * kt][1];
                a[2] = (kt < 6) ? spk[mt][2 * kt + 1][0] : biasA;
                a[3] = (kt < 6) ? spk[mt][2 * kt + 1][1] : biasA;
#pragma unroll
                for (int np = 0; np < NTP; ++np) {
                    if (kt == 0) {
                        mma16816i(acc[mt][2 * np], a, b[np][0], b[np][1], zc);
                        if (2 * np + 1 < NT)
                            mma16816i(acc[mt][2 * np + 1], a, b[np][2], b[np][3], zc);
                    } else {
                        mma16816(acc[mt][2 * np], a, b[np][0], b[np][1]);
                        if (2 * np + 1 < NT)
                            mma16816(acc[mt][2 * np + 1], a, b[np][2], b[np][3]);
                    }
                }
            }
        }

        // ---- stage3: g2 = (1 - h2^2/2) * w3 -> GEMM2 A-fragments ----
        uint32_t af[2][KT][4];
#pragma unroll
        for (int nt = 0; nt < NT; ++nt) {
            const uint32_t wpk = w3pk[4 * nt + (l & 3)];
#pragma unroll
            for (int mt = 0; mt < 2; ++mt)
                g2_tile(acc[mt][nt], wpk, &af[mt][nt >> 1][2 * (nt & 1)]);
        }
#pragma unroll
        for (int mt = 0; mt < 2; ++mt) { af[mt][6][2] = 0u; af[mt][6][3] = 0u; }

        // ---- GEMM2: GC = G2 @ W2 (B = trans-ldsm of W2 tile), kt-outer ----
#pragma unroll
        for (int kt = 0; kt < KT; ++kt) {
            uint32_t b[NTP][4];
#pragma unroll
            for (int np = 0; np < NTP; ++np)
                ldsm4t(b[np], bW2t + 16 * kt * SPB + 32 * np);
#pragma unroll
            for (int mt = 0; mt < 2; ++mt)
#pragma unroll
                for (int np = 0; np < NTP; ++np) {
                    if (kt == 0) {
                        mma16816i(acc[mt][2 * np], af[mt][0], b[np][0], b[np][1], zc);
                        if (2 * np + 1 < NT)
                            mma16816i(acc[mt][2 * np + 1], af[mt][0], b[np][2], b[np][3], zc);
                    } else {
                        mma16816(acc[mt][2 * np], af[mt][kt], b[np][0], b[np][1]);
                        if (2 * np + 1 < NT)
                            mma16816(acc[mt][2 * np + 1], af[mt][kt], b[np][2], b[np][3]);
                    }
                }
        }

        // ---- all warps done with W2/W1H/W3: prefetch next pass ----
        __syncthreads();
        if (pass + 1 < NPASS) {
            const unsigned char* src = g_blob[pass + 1];
            for (int i = tid; i < REGA_BYTES / 16; i += TPB)
                cp16(sbase + SM_W2 + 16 * i, src + 16 * i);
            const uint32_t dstG = sbase + (((pass + 1) & 1) ? SM_W1G1 : SM_W1G0);
            for (int i = tid; i < 3840 / 16; i += TPB)
                cp16(dstG + 16 * i, src + OB_W1G + 16 * i);
            asm volatile("cp.async.commit_group;");
        }

        // ---- stage5 + branch diff: dA = g1(t) - g1(0) in bf16 ----
        uint32_t dA[KT][4];
#pragma unroll
        for (int kt = 0; kt < KT; ++kt) {
#pragma unroll
            for (int sub = 0; sub < 2; ++sub) {
                const int nt = 2 * kt + sub;
                if (nt < NT) {
                    uint32_t o0[2], o1[2];
                    g1_tile(acc[0][nt], sScr + nt * 256, o0);
                    g1_tile(acc[1][nt], sScr + (NT + nt) * 256, o1);
                    dA[kt][2 * sub]     = hsub2u(o0[0], o1[0]);
                    dA[kt][2 * sub + 1] = hsub2u(o0[1], o1[1]);
                } else {
                    dA[kt][2 * sub] = 0u; dA[kt][2 * sub + 1] = 0u;
                }
            }
        }

        // ---- GEMM3: gg = (G1(t)-G1(0)) @ W1[:, :2], single 7-MMA GEMM ----
        float acc3[4];
        {
            const uint32_t bW1g = sbase + ((pass & 1) ? SM_W1G1 : SM_W1G0) + bW1gL;
#pragma unroll
            for (int kt = 0; kt < KT; ++kt) {
                uint32_t bg[4];
                ldsm4(bg, bW1g + 32 * kt);
                if (kt == 0) mma16816i(acc3, dA[0], bg[0], bg[1], zc);
                else         mma16816 (acc3, dA[kt], bg[0], bg[1]);
            }
        }

        // ---- broadcast gg within warp, update state ----
        const int h = 4 * (el & 7);
        float s0 = __shfl_sync(0xffffffffu, acc3[0], h);
        float s1 = __shfl_sync(0xffffffffu, acc3[1], h);
        float s2 = __shfl_sync(0xffffffffu, acc3[2], h);
        float s3 = __shfl_sync(0xffffffffu, acc3[3], h);
        const float g0 = (el < 8) ? s0 : s2;
        const float g1 = (el < 8) ? s1 : s3;
        if (ph == 0) { p0 -= g0; p1 -= g1; }
        else         { q0 += g0; q1 += g1; }
    }

    if (l < 16)
        reinterpret_cast<float4*>(out)[grow] = make_float4(q0, q1, p0, p1);
}

// ------------------------------------------------------------------
extern "C" void kernel_launch(void* const* d_in, const int* in_sizes, int n_in,
                              void* d_out, int out_size)
{
    const float* z   = (const float*)d_in[0];
    const float* t   = (const float*)d_in[1];
    const float* Wq1 = (const float*)d_in[2];
    const float* bq1 = (const float*)d_in[3];
    const float* Wq2 = (const float*)d_in[4];
    const float* bq2 = (const float*)d_in[5];
    const float* wq3 = (const float*)d_in[6];
    const float* Wp1 = (const float*)d_in[7];
    const float* bp1 = (const float*)d_in[8];
    const float* Wp2 = (const float*)d_in[9];
    const float* bp2 = (const float*)d_in[10];
    const float* wp3 = (const float*)d_in[11];
    float* out = (float*)d_out;

    cudaFuncSetAttribute(sympnet_mma_kernel,
                         cudaFuncAttributeMaxDynamicSharedMemorySize, SM_TOTAL);

    prep_kernel<<<NPASS, 256>>>(Wq1, bq1, Wq2, bq2, wq3, Wp1, bp1, Wp2, bp2, wp3);
    sympnet_mma_kernel<<<NBATCH / TILEB, TPB, SM_TOTAL>>>(z, t, out);
}